// round 7
// baseline (speedup 1.0000x reference)
#include <cuda_runtime.h>
#include <cuda_bf16.h>

// Problem constants
#define B     16
#define N1P   1024
#define N2P   4096
#define N1    (B * N1P)      // 16384 queries
#define N2    (B * N2P)      // 65536 sources
#define D_IN  64
#define H1    128
#define H2    256
#define KNB   32
#define R2    0.04f

#define NROWS 48             // 32 nbrs + self + pad(dup self) -> 3 m-tiles of 16
#define MT    3              // m-tiles per query
#define KS    16             // k-steps (128 / 8)

typedef unsigned int uint;

// ---------------- scratch (static device globals; no allocations) ----------
__device__ float g_y2[(size_t)N2 * H1];     // x2 @ W1[:64] + b1  (33.5 MB)
__device__ int   g_nbr[(size_t)N1 * KNB];
__device__ int   g_cnt[N1];
__device__ uint  g_bh[KS * 8 * 32 * 8];     // W2 tf32-hi fragments (128 KB)
__device__ uint  g_bl[KS * 8 * 32 * 8];     // W2 tf32-lo fragments (128 KB)

// ---------------- tf32 helpers ---------------------------------------------
__device__ __forceinline__ uint tf32r(float f) {
    uint u; asm("cvt.rna.tf32.f32 %0, %1;" : "=r"(u) : "f"(f)); return u;
}
__device__ __forceinline__ void split_tf32(float v, uint& hi, uint& lo) {
    hi = tf32r(v);
    lo = tf32r(v - __uint_as_float(hi));
}
__device__ __forceinline__ void mma_tf32(float* c, uint a0, uint a1, uint a2,
                                         uint a3, uint b0, uint b1) {
    asm("mma.sync.aligned.m16n8k8.row.col.f32.tf32.tf32.f32 "
        "{%0,%1,%2,%3},{%4,%5,%6,%7},{%8,%9},{%0,%1,%2,%3};"
        : "+f"(c[0]), "+f"(c[1]), "+f"(c[2]), "+f"(c[3])
        : "r"(a0), "r"(a1), "r"(a2), "r"(a3), "r"(b0), "r"(b1));
}

// ================ kernel 1: y2 = x2 @ W1[0:64] + b1 ========================
#define PR_ROWS 64
__global__ __launch_bounds__(128) void precompute_y2_kernel(
    const float* __restrict__ x2, const float* __restrict__ W1,
    const float* __restrict__ b1)
{
    __shared__ __align__(16) float xs[PR_ROWS * D_IN];
    int c = threadIdx.x;
    float w[D_IN];
    #pragma unroll
    for (int d = 0; d < D_IN; ++d) w[d] = W1[d * H1 + c];
    float bc = b1[c];

    size_t rbase = (size_t)blockIdx.x * PR_ROWS;
    const float4* src  = (const float4*)(x2 + rbase * D_IN);
    float4*       dst4 = (float4*)xs;
    for (int i = c; i < PR_ROWS * D_IN / 4; i += 128) dst4[i] = src[i];
    __syncthreads();

    for (int r = 0; r < PR_ROWS; ++r) {
        const float4* xr = (const float4*)(xs + r * D_IN);
        float a = bc;
        #pragma unroll
        for (int t = 0; t < D_IN / 4; ++t) {
            float4 xv = xr[t];
            a = fmaf(xv.x, w[4 * t],     a);
            a = fmaf(xv.y, w[4 * t + 1], a);
            a = fmaf(xv.z, w[4 * t + 2], a);
            a = fmaf(xv.w, w[4 * t + 3], a);
        }
        g_y2[(rbase + r) * H1 + c] = a;
    }
}

// ================ kernel 1b: W2 -> tf32 hi/lo fragment layout ==============
// idx i -> [((ks*8+g)*32 + t)*8 + w]; w = nt*2+word;
// source element: W2[8*ks + (t%4) + 4*word][g*32 + nt*8 + t/4]
__global__ __launch_bounds__(256) void bfrag_kernel(const float* __restrict__ W2)
{
    int i = blockIdx.x * 256 + threadIdx.x;         // 32768 total
    int w    = i & 7;
    int t    = (i >> 3) & 31;
    int g    = (i >> 8) & 7;
    int ks   = i >> 11;
    int nt   = w >> 1;
    int word = w & 1;
    int k = 8 * ks + (t & 3) + 4 * word;
    int n = g * 32 + nt * 8 + (t >> 2);
    uint hi, lo;
    split_tf32(W2[k * H2 + n], hi, lo);
    g_bh[i] = hi;
    g_bl[i] = lo;
}

// ================ kernel 2: ball query (warp per query) ====================
__global__ void ball_query_kernel(const float* __restrict__ pos1,
                                  const float* __restrict__ pos2)
{
    int gw   = (blockIdx.x * blockDim.x + threadIdx.x) >> 5;
    int lane = threadIdx.x & 31;
    if (gw >= N1) return;
    int q = gw;
    float qx = pos1[3 * q], qy = pos1[3 * q + 1], qz = pos1[3 * q + 2];
    float qn = qx * qx + qy * qy + qz * qz;
    int base = (q >> 10) << 12;
    int cnt = 0;
    for (int chunk = 0; chunk < N2P / 32; ++chunk) {
        int s = base + chunk * 32 + lane;
        float sx = pos2[3 * s], sy = pos2[3 * s + 1], sz = pos2[3 * s + 2];
        float sn  = sx * sx + sy * sy + sz * sz;
        float dot = qx * sx + qy * sy + qz * sz;
        float sq  = qn + sn - 2.0f * dot;
        bool inb = (sq <= R2);
        unsigned m = __ballot_sync(0xffffffffu, inb);
        if (inb) {
            int slot = cnt + __popc(m & ((1u << lane) - 1u));
            if (slot < KNB) g_nbr[(size_t)q * KNB + slot] = s;
        }
        cnt += __popc(m);
        if (cnt >= KNB) break;
    }
    if (lane == 0) g_cnt[q] = (cnt < KNB) ? cnt : KNB;
}

// ================ kernel 3: per-query MLP via split-tf32 mma.sync ==========
// 256 threads / query. Pass 1: A = m1 (48 x 128) raw fp32, fragment-order smem.
// Pass 2: warp g owns cols [g*32,g*32+32); acc += ahi*bhi + ahi*blo + alo*bhi.
__global__ __launch_bounds__(256) void conv_kernel(
    const float* __restrict__ pos1, const float* __restrict__ pos2,
    const float* __restrict__ W1,   const float* __restrict__ b2,
    float* __restrict__ out)
{
    __shared__ __align__(16) float afrag[MT * KS * 32 * 4];  // 24 KB, raw fp32
    __shared__ int   jb[NROWS];
    __shared__ float dxs[NROWS], dys[NROWS], dzs[NROWS];

    int q   = blockIdx.x;
    int tid = threadIdx.x;
    int cnt = g_cnt[q];

    if (tid < NROWS) {
        int n = tid;
        int j = (n < cnt) ? g_nbr[(size_t)q * KNB + n] : q;  // self / pad->self
        jb[n] = j;
        // NOTE: self & pad rows use pos2[q] - pos1[q] (NOT zero) — this
        // exactly duplicates the true self-loop row, so max is unaffected.
        float px = pos1[3 * q], py = pos1[3 * q + 1], pz = pos1[3 * q + 2];
        dxs[n] = pos2[3 * j]     - px;
        dys[n] = pos2[3 * j + 1] - py;
        dzs[n] = pos2[3 * j + 2] - pz;
    }
    __syncthreads();

    // ---- pass 1: rows split between thread halves; col = tid % 128 ----
    {
        int c  = tid & 127;
        int rh = tid >> 7;                  // 0 -> rows 0..23, 1 -> 24..47
        float wx = W1[64 * H1 + c], wy = W1[65 * H1 + c], wz = W1[66 * H1 + c];
        int ks = c >> 3;
        #pragma unroll
        for (int r = 0; r < 24; ++r) {
            int n = rh * 24 + r;
            float t = g_y2[(size_t)jb[n] * H1 + c];
            t = fmaf(dxs[n], wx, t);
            t = fmaf(dys[n], wy, t);
            t = fmaf(dzs[n], wz, t);
            float v = fmaxf(t, 0.0f);
            int mt = n >> 4;
            int rl = n & 15;
            int tt = ((rl & 7) << 2) | (c & 3);
            int w  = (rl >> 3) | (((c >> 2) & 1) << 1);
            afrag[((mt * KS + ks) * 32 + tt) * 4 + w] = v;
        }
    }
    __syncthreads();

    // ---- pass 2: 3-term split-tf32 mma ----
    int g = tid >> 5;          // warp = n-group (32 cols)
    int t = tid & 31;

    float acc[MT][4][4];
    #pragma unroll
    for (int mt = 0; mt < MT; ++mt)
        #pragma unroll
        for (int nt = 0; nt < 4; ++nt)
            #pragma unroll
            for (int i = 0; i < 4; ++i) acc[mt][nt][i] = 0.0f;

    #pragma unroll 4
    for (int ks = 0; ks < KS; ++ks) {
        uint ah[MT][4], al[MT][4];
        #pragma unroll
        for (int mt = 0; mt < MT; ++mt) {
            float4 av = *(const float4*)&afrag[((mt * KS + ks) * 32 + t) * 4];
            split_tf32(av.x, ah[mt][0], al[mt][0]);
            split_tf32(av.y, ah[mt][1], al[mt][1]);
            split_tf32(av.z, ah[mt][2], al[mt][2]);
            split_tf32(av.w, ah[mt][3], al[mt][3]);
        }
        size_t bofs = ((size_t)(ks * 8 + g) * 32 + t) * 8;
        uint4 bh01 = *(const uint4*)&g_bh[bofs];
        uint4 bh23 = *(const uint4*)&g_bh[bofs + 4];
        uint4 bl01 = *(const uint4*)&g_bl[bofs];
        uint4 bl23 = *(const uint4*)&g_bl[bofs + 4];
        #pragma unroll
        for (int mt = 0; mt < MT; ++mt) {
            // term 1: ahi * bhi
            mma_tf32(acc[mt][0], ah[mt][0], ah[mt][1], ah[mt][2], ah[mt][3], bh01.x, bh01.y);
            mma_tf32(acc[mt][1], ah[mt][0], ah[mt][1], ah[mt][2], ah[mt][3], bh01.z, bh01.w);
            mma_tf32(acc[mt][2], ah[mt][0], ah[mt][1], ah[mt][2], ah[mt][3], bh23.x, bh23.y);
            mma_tf32(acc[mt][3], ah[mt][0], ah[mt][1], ah[mt][2], ah[mt][3], bh23.z, bh23.w);
            // term 2: ahi * blo
            mma_tf32(acc[mt][0], ah[mt][0], ah[mt][1], ah[mt][2], ah[mt][3], bl01.x, bl01.y);
            mma_tf32(acc[mt][1], ah[mt][0], ah[mt][1], ah[mt][2], ah[mt][3], bl01.z, bl01.w);
            mma_tf32(acc[mt][2], ah[mt][0], ah[mt][1], ah[mt][2], ah[mt][3], bl23.x, bl23.y);
            mma_tf32(acc[mt][3], ah[mt][0], ah[mt][1], ah[mt][2], ah[mt][3], bl23.z, bl23.w);
            // term 3: alo * bhi
            mma_tf32(acc[mt][0], al[mt][0], al[mt][1], al[mt][2], al[mt][3], bh01.x, bh01.y);
            mma_tf32(acc[mt][1], al[mt][0], al[mt][1], al[mt][2], al[mt][3], bh01.z, bh01.w);
            mma_tf32(acc[mt][2], al[mt][0], al[mt][1], al[mt][2], al[mt][3], bh23.x, bh23.y);
            mma_tf32(acc[mt][3], al[mt][0], al[mt][1], al[mt][2], al[mt][3], bh23.z, bh23.w);
        }
    }

    // ---- epilogue: max over rows (pads are dup self -> no masking) ----
    #pragma unroll
    for (int nt = 0; nt < 4; ++nt) {
        float vA = acc[0][nt][0], vB = acc[0][nt][1];
        vA = fmaxf(vA, acc[0][nt][2]);  vB = fmaxf(vB, acc[0][nt][3]);
        #pragma unroll
        for (int mt = 1; mt < MT; ++mt) {
            vA = fmaxf(vA, fmaxf(acc[mt][nt][0], acc[mt][nt][2]));
            vB = fmaxf(vB, fmaxf(acc[mt][nt][1], acc[mt][nt][3]));
        }
        #pragma unroll
        for (int o = 4; o < 32; o <<= 1) {
            vA = fmaxf(vA, __shfl_xor_sync(0xffffffffu, vA, o));
            vB = fmaxf(vB, __shfl_xor_sync(0xffffffffu, vB, o));
        }
        if (t < 4) {
            int colA = g * 32 + nt * 8 + t * 2;
            out[(size_t)q * H2 + colA]     = fmaxf(vA + b2[colA], 0.0f);
            out[(size_t)q * H2 + colA + 1] = fmaxf(vB + b2[colA + 1], 0.0f);
        }
    }
}

// =========================== launcher ======================================
extern "C" void kernel_launch(void* const* d_in, const int* in_sizes, int n_in,
                              void* d_out, int out_size)
{
    // inputs: 0:x1 1:pos1 2:batch1(i64) 3:x2 4:pos2 5:batch2(i64)
    //         6:W1[67,128] 7:b1[128] 8:W2[128,256] 9:b2[256]
    const float* pos1 = (const float*)d_in[1];
    const float* x2   = (const float*)d_in[3];
    const float* pos2 = (const float*)d_in[4];
    const float* W1   = (const float*)d_in[6];
    const float* b1   = (const float*)d_in[7];
    const float* W2   = (const float*)d_in[8];
    const float* b2   = (const float*)d_in[9];
    float* out = (float*)d_out;

    precompute_y2_kernel<<<N2 / PR_ROWS, 128>>>(x2, W1, b1);
    bfrag_kernel<<<KS * 8 * 32 * 8 / 256, 256>>>(W2);
    ball_query_kernel<<<(N1 * 32 + 255) / 256, 256>>>(pos1, pos2);
    conv_kernel<<<N1, 256>>>(pos1, pos2, W1, b2, out);
}

// round 8
// speedup vs baseline: 1.4467x; 1.4467x over previous
#include <cuda_runtime.h>
#include <cuda_bf16.h>

// Problem constants
#define B     16
#define N1P   1024
#define N2P   4096
#define N1    (B * N1P)      // 16384 queries
#define N2    (B * N2P)      // 65536 sources
#define D_IN  64
#define H1    128
#define H2    256
#define KNB   32
#define R2    0.04f

#define NROWS 48             // 32 nbrs + self + pad(dup self) -> 3 m-tiles of 16
#define MT    3              // m-tiles per query
#define KS    16             // k-steps (128 / 8)

typedef unsigned int uint;

// ---------------- scratch (static device globals; no allocations) ----------
__device__ float g_y2[(size_t)N2 * H1];     // x2 @ W1[:64] + b1  (33.5 MB)
__device__ int   g_nbr[(size_t)N1 * KNB];
__device__ int   g_cnt[N1];
__device__ uint  g_bh[KS * 8 * 32 * 8];     // W2 tf32 fragments (128 KB)

// ---------------- tf32 helpers ---------------------------------------------
__device__ __forceinline__ uint tf32r(float f) {
    uint u; asm("cvt.rna.tf32.f32 %0, %1;" : "=r"(u) : "f"(f)); return u;
}
__device__ __forceinline__ void mma_tf32(float* c, uint a0, uint a1, uint a2,
                                         uint a3, uint b0, uint b1) {
    asm("mma.sync.aligned.m16n8k8.row.col.f32.tf32.tf32.f32 "
        "{%0,%1,%2,%3},{%4,%5,%6,%7},{%8,%9},{%0,%1,%2,%3};"
        : "+f"(c[0]), "+f"(c[1]), "+f"(c[2]), "+f"(c[3])
        : "r"(a0), "r"(a1), "r"(a2), "r"(a3), "r"(b0), "r"(b1));
}

// ================ kernel 1: y2 = x2 @ W1[0:64] + b1 ========================
#define PR_ROWS 64
__global__ __launch_bounds__(128) void precompute_y2_kernel(
    const float* __restrict__ x2, const float* __restrict__ W1,
    const float* __restrict__ b1)
{
    __shared__ __align__(16) float xs[PR_ROWS * D_IN];
    int c = threadIdx.x;
    float w[D_IN];
    #pragma unroll
    for (int d = 0; d < D_IN; ++d) w[d] = W1[d * H1 + c];
    float bc = b1[c];

    size_t rbase = (size_t)blockIdx.x * PR_ROWS;
    const float4* src  = (const float4*)(x2 + rbase * D_IN);
    float4*       dst4 = (float4*)xs;
    for (int i = c; i < PR_ROWS * D_IN / 4; i += 128) dst4[i] = src[i];
    __syncthreads();

    for (int r = 0; r < PR_ROWS; ++r) {
        const float4* xr = (const float4*)(xs + r * D_IN);
        float a = bc;
        #pragma unroll
        for (int t = 0; t < D_IN / 4; ++t) {
            float4 xv = xr[t];
            a = fmaf(xv.x, w[4 * t],     a);
            a = fmaf(xv.y, w[4 * t + 1], a);
            a = fmaf(xv.z, w[4 * t + 2], a);
            a = fmaf(xv.w, w[4 * t + 3], a);
        }
        g_y2[(rbase + r) * H1 + c] = a;
    }
}

// ================ kernel 1b: W2 -> tf32 fragment layout ====================
// idx i -> [((ks*8+g)*32 + t)*8 + w]; w = nt*2+word;
// source element: W2[8*ks + (t%4) + 4*word][g*32 + nt*8 + t/4]
__global__ __launch_bounds__(256) void bfrag_kernel(const float* __restrict__ W2)
{
    int i = blockIdx.x * 256 + threadIdx.x;         // 32768 total
    int w    = i & 7;
    int t    = (i >> 3) & 31;
    int g    = (i >> 8) & 7;
    int ks   = i >> 11;
    int nt   = w >> 1;
    int word = w & 1;
    int k = 8 * ks + (t & 3) + 4 * word;
    int n = g * 32 + nt * 8 + (t >> 2);
    g_bh[i] = tf32r(W2[k * H2 + n]);
}

// ================ kernel 2: ball query (warp per query) ====================
__global__ void ball_query_kernel(const float* __restrict__ pos1,
                                  const float* __restrict__ pos2)
{
    int gw   = (blockIdx.x * blockDim.x + threadIdx.x) >> 5;
    int lane = threadIdx.x & 31;
    if (gw >= N1) return;
    int q = gw;
    float qx = pos1[3 * q], qy = pos1[3 * q + 1], qz = pos1[3 * q + 2];
    float qn = qx * qx + qy * qy + qz * qz;
    int base = (q >> 10) << 12;
    int cnt = 0;
    for (int chunk = 0; chunk < N2P / 32; ++chunk) {
        int s = base + chunk * 32 + lane;
        float sx = pos2[3 * s], sy = pos2[3 * s + 1], sz = pos2[3 * s + 2];
        float sn  = sx * sx + sy * sy + sz * sz;
        float dot = qx * sx + qy * sy + qz * sz;
        float sq  = qn + sn - 2.0f * dot;
        bool inb = (sq <= R2);
        unsigned m = __ballot_sync(0xffffffffu, inb);
        if (inb) {
            int slot = cnt + __popc(m & ((1u << lane) - 1u));
            if (slot < KNB) g_nbr[(size_t)q * KNB + slot] = s;
        }
        cnt += __popc(m);
        if (cnt >= KNB) break;
    }
    if (lane == 0) g_cnt[q] = (cnt < KNB) ? cnt : KNB;
}

// ================ kernel 3: per-query MLP via tf32 mma.sync ================
// 256 threads / query. Pass 1: A = m1 (48 x 128) pre-converted tf32 in smem
// (fragment order). Pass 2: warp g owns cols [g*32,g*32+32); 12 mma per ks.
__global__ __launch_bounds__(256) void conv_kernel(
    const float* __restrict__ pos1, const float* __restrict__ pos2,
    const float* __restrict__ W1,   const float* __restrict__ b2,
    float* __restrict__ out)
{
    __shared__ __align__(16) uint afrag[MT * KS * 32 * 4];  // 24 KB, tf32 bits
    __shared__ int   jb[NROWS];
    __shared__ float dxs[NROWS], dys[NROWS], dzs[NROWS];

    int q   = blockIdx.x;
    int tid = threadIdx.x;
    int cnt = g_cnt[q];

    if (tid < NROWS) {
        int n = tid;
        int j = (n < cnt) ? g_nbr[(size_t)q * KNB + n] : q;  // self / pad->self
        jb[n] = j;
        // self & pad rows use pos2[q] - pos1[q] (NOT zero): exact duplicate of
        // the true self-loop row, so the max is unaffected by padding.
        float px = pos1[3 * q], py = pos1[3 * q + 1], pz = pos1[3 * q + 2];
        dxs[n] = pos2[3 * j]     - px;
        dys[n] = pos2[3 * j + 1] - py;
        dzs[n] = pos2[3 * j + 2] - pz;
    }
    __syncthreads();

    // ---- pass 1: rows split between thread halves; col = tid % 128 ----
    {
        int c  = tid & 127;
        int rh = tid >> 7;                  // 0 -> rows 0..23, 1 -> 24..47
        float wx = W1[64 * H1 + c], wy = W1[65 * H1 + c], wz = W1[66 * H1 + c];
        int ks = c >> 3;
        #pragma unroll
        for (int r = 0; r < 24; ++r) {
            int n = rh * 24 + r;
            float t = g_y2[(size_t)jb[n] * H1 + c];
            t = fmaf(dxs[n], wx, t);
            t = fmaf(dys[n], wy, t);
            t = fmaf(dzs[n], wz, t);
            float v = fmaxf(t, 0.0f);
            int mt = n >> 4;
            int rl = n & 15;
            int tt = ((rl & 7) << 2) | (c & 3);
            int w  = (rl >> 3) | (((c >> 2) & 1) << 1);
            afrag[((mt * KS + ks) * 32 + tt) * 4 + w] = tf32r(v);
        }
    }
    __syncthreads();

    // ---- pass 2: tf32 mma, 12 per k-step ----
    int g = tid >> 5;          // warp = n-group (32 cols)
    int t = tid & 31;

    float acc[MT][4][4];
    #pragma unroll
    for (int mt = 0; mt < MT; ++mt)
        #pragma unroll
        for (int nt = 0; nt < 4; ++nt)
            #pragma unroll
            for (int i = 0; i < 4; ++i) acc[mt][nt][i] = 0.0f;

    #pragma unroll 4
    for (int ks = 0; ks < KS; ++ks) {
        uint4 a[MT];
        #pragma unroll
        for (int mt = 0; mt < MT; ++mt)
            a[mt] = *(const uint4*)&afrag[((mt * KS + ks) * 32 + t) * 4];
        size_t bofs = ((size_t)(ks * 8 + g) * 32 + t) * 8;
        uint4 b01 = *(const uint4*)&g_bh[bofs];
        uint4 b23 = *(const uint4*)&g_bh[bofs + 4];
        #pragma unroll
        for (int mt = 0; mt < MT; ++mt) {
            mma_tf32(acc[mt][0], a[mt].x, a[mt].y, a[mt].z, a[mt].w, b01.x, b01.y);
            mma_tf32(acc[mt][1], a[mt].x, a[mt].y, a[mt].z, a[mt].w, b01.z, b01.w);
            mma_tf32(acc[mt][2], a[mt].x, a[mt].y, a[mt].z, a[mt].w, b23.x, b23.y);
            mma_tf32(acc[mt][3], a[mt].x, a[mt].y, a[mt].z, a[mt].w, b23.z, b23.w);
        }
    }

    // ---- epilogue: max over rows (pads are dup self -> no masking) ----
    #pragma unroll
    for (int nt = 0; nt < 4; ++nt) {
        float vA = acc[0][nt][0], vB = acc[0][nt][1];
        vA = fmaxf(vA, acc[0][nt][2]);  vB = fmaxf(vB, acc[0][nt][3]);
        #pragma unroll
        for (int mt = 1; mt < MT; ++mt) {
            vA = fmaxf(vA, fmaxf(acc[mt][nt][0], acc[mt][nt][2]));
            vB = fmaxf(vB, fmaxf(acc[mt][nt][1], acc[mt][nt][3]));
        }
        #pragma unroll
        for (int o = 4; o < 32; o <<= 1) {
            vA = fmaxf(vA, __shfl_xor_sync(0xffffffffu, vA, o));
            vB = fmaxf(vB, __shfl_xor_sync(0xffffffffu, vB, o));
        }
        if (t < 4) {
            int colA = g * 32 + nt * 8 + t * 2;
            out[(size_t)q * H2 + colA]     = fmaxf(vA + b2[colA], 0.0f);
            out[(size_t)q * H2 + colA + 1] = fmaxf(vB + b2[colA + 1], 0.0f);
        }
    }
}

// =========================== launcher ======================================
extern "C" void kernel_launch(void* const* d_in, const int* in_sizes, int n_in,
                              void* d_out, int out_size)
{
    // inputs: 0:x1 1:pos1 2:batch1(i64) 3:x2 4:pos2 5:batch2(i64)
    //         6:W1[67,128] 7:b1[128] 8:W2[128,256] 9:b2[256]
    const float* pos1 = (const float*)d_in[1];
    const float* x2   = (const float*)d_in[3];
    const float* pos2 = (const float*)d_in[4];
    const float* W1   = (const float*)d_in[6];
    const float* b1   = (const float*)d_in[7];
    const float* W2   = (const float*)d_in[8];
    const float* b2   = (const float*)d_in[9];
    float* out = (float*)d_out;

    precompute_y2_kernel<<<N2 / PR_ROWS, 128>>>(x2, W1, b1);
    bfrag_kernel<<<KS * 8 * 32 * 8 / 256, 256>>>(W2);
    ball_query_kernel<<<(N1 * 32 + 255) / 256, 256>>>(pos1, pos2);
    conv_kernel<<<N1, 256>>>(pos1, pos2, W1, b2, out);
}

// round 9
// speedup vs baseline: 1.6345x; 1.1298x over previous
#include <cuda_runtime.h>
#include <cuda_bf16.h>

// Problem constants
#define B     16
#define N1P   1024
#define N2P   4096
#define N1    (B * N1P)      // 16384 queries
#define N2    (B * N2P)      // 65536 sources
#define D_IN  64
#define H1    128
#define H2    256
#define KNB   32
#define R2    0.04f

#define NROWS 48             // 32 nbrs + self + pad(dup self) -> 3 m-tiles of 16
#define MT    3              // m-tiles per query
#define KS    16             // k-steps (128 / 8)
#define CT    512            // conv threads (16 warps x 16 cols)

typedef unsigned int uint;

// ---------------- scratch (static device globals; no allocations) ----------
__device__ float g_y2[(size_t)N2 * H1];     // x2 @ W1[:64] + b1  (33.5 MB)
__device__ int   g_nbr[(size_t)N1 * KNB];
__device__ int   g_cnt[N1];
__device__ uint  g_bh[KS * 8 * 32 * 8];     // W2 tf32 fragments (128 KB)

// ---------------- tf32 helpers ---------------------------------------------
__device__ __forceinline__ uint tf32r(float f) {
    uint u; asm("cvt.rna.tf32.f32 %0, %1;" : "=r"(u) : "f"(f)); return u;
}
__device__ __forceinline__ void mma_tf32(float* c, uint a0, uint a1, uint a2,
                                         uint a3, uint b0, uint b1) {
    asm("mma.sync.aligned.m16n8k8.row.col.f32.tf32.tf32.f32 "
        "{%0,%1,%2,%3},{%4,%5,%6,%7},{%8,%9},{%0,%1,%2,%3};"
        : "+f"(c[0]), "+f"(c[1]), "+f"(c[2]), "+f"(c[3])
        : "r"(a0), "r"(a1), "r"(a2), "r"(a3), "r"(b0), "r"(b1));
}

// ================ kernel 1: y2 = x2 @ W1[0:64] + b1 ========================
#define PR_ROWS 64
__global__ __launch_bounds__(128) void precompute_y2_kernel(
    const float* __restrict__ x2, const float* __restrict__ W1,
    const float* __restrict__ b1)
{
    __shared__ __align__(16) float xs[PR_ROWS * D_IN];
    int c = threadIdx.x;
    float w[D_IN];
    #pragma unroll
    for (int d = 0; d < D_IN; ++d) w[d] = W1[d * H1 + c];
    float bc = b1[c];

    size_t rbase = (size_t)blockIdx.x * PR_ROWS;
    const float4* src  = (const float4*)(x2 + rbase * D_IN);
    float4*       dst4 = (float4*)xs;
    for (int i = c; i < PR_ROWS * D_IN / 4; i += 128) dst4[i] = src[i];
    __syncthreads();

    for (int r = 0; r < PR_ROWS; ++r) {
        const float4* xr = (const float4*)(xs + r * D_IN);
        float a = bc;
        #pragma unroll
        for (int t = 0; t < D_IN / 4; ++t) {
            float4 xv = xr[t];
            a = fmaf(xv.x, w[4 * t],     a);
            a = fmaf(xv.y, w[4 * t + 1], a);
            a = fmaf(xv.z, w[4 * t + 2], a);
            a = fmaf(xv.w, w[4 * t + 3], a);
        }
        g_y2[(rbase + r) * H1 + c] = a;
    }
}

// ================ kernel 1b: W2 -> tf32 fragment layout ====================
// idx i -> [((ks*8+G)*32 + t)*8 + w]; w = NT*2+word;  (G: 32-col group 0..7)
// source element: W2[8*ks + (t%4) + 4*word][G*32 + NT*8 + t/4]
__global__ __launch_bounds__(256) void bfrag_kernel(const float* __restrict__ W2)
{
    int i = blockIdx.x * 256 + threadIdx.x;         // 32768 total
    int w    = i & 7;
    int t    = (i >> 3) & 31;
    int g    = (i >> 8) & 7;
    int ks   = i >> 11;
    int nt   = w >> 1;
    int word = w & 1;
    int k = 8 * ks + (t & 3) + 4 * word;
    int n = g * 32 + nt * 8 + (t >> 2);
    g_bh[i] = tf32r(W2[k * H2 + n]);
}

// ================ kernel 2: ball query (warp per query) ====================
__global__ void ball_query_kernel(const float* __restrict__ pos1,
                                  const float* __restrict__ pos2)
{
    int gw   = (blockIdx.x * blockDim.x + threadIdx.x) >> 5;
    int lane = threadIdx.x & 31;
    if (gw >= N1) return;
    int q = gw;
    float qx = pos1[3 * q], qy = pos1[3 * q + 1], qz = pos1[3 * q + 2];
    float qn = qx * qx + qy * qy + qz * qz;
    int base = (q >> 10) << 12;
    int cnt = 0;
    for (int chunk = 0; chunk < N2P / 32; ++chunk) {
        int s = base + chunk * 32 + lane;
        float sx = pos2[3 * s], sy = pos2[3 * s + 1], sz = pos2[3 * s + 2];
        float sn  = sx * sx + sy * sy + sz * sz;
        float dot = qx * sx + qy * sy + qz * sz;
        float sq  = qn + sn - 2.0f * dot;
        bool inb = (sq <= R2);
        unsigned m = __ballot_sync(0xffffffffu, inb);
        if (inb) {
            int slot = cnt + __popc(m & ((1u << lane) - 1u));
            if (slot < KNB) g_nbr[(size_t)q * KNB + slot] = s;
        }
        cnt += __popc(m);
        if (cnt >= KNB) break;
    }
    if (lane == 0) g_cnt[q] = (cnt < KNB) ? cnt : KNB;
}

// ================ kernel 3: per-query MLP via tf32 mma.sync ================
// 512 threads / query, 16 warps; warp g owns 16 cols (2 n-tiles of 8).
// Pass 1: A = m1 (48 x 128) pre-converted tf32, fragment order in smem.
// Pass 2: 6 mma per k-step per warp; 32 resident warps/SM for latency hiding.
__global__ __launch_bounds__(CT, 2) void conv_kernel(
    const float* __restrict__ pos1, const float* __restrict__ pos2,
    const float* __restrict__ W1,   const float* __restrict__ b2,
    float* __restrict__ out)
{
    __shared__ __align__(16) uint afrag[MT * KS * 32 * 4];  // 24 KB, tf32 bits
    __shared__ int   jb[NROWS];
    __shared__ float dxs[NROWS], dys[NROWS], dzs[NROWS];

    int q   = blockIdx.x;
    int tid = threadIdx.x;
    int cnt = g_cnt[q];

    if (tid < NROWS) {
        int n = tid;
        int j = (n < cnt) ? g_nbr[(size_t)q * KNB + n] : q;  // self / pad->self
        jb[n] = j;
        // self & pad rows use pos2[q] - pos1[q] (NOT zero): exact duplicate of
        // the true self-loop row, so the max is unaffected by padding.
        float px = pos1[3 * q], py = pos1[3 * q + 1], pz = pos1[3 * q + 2];
        dxs[n] = pos2[3 * j]     - px;
        dys[n] = pos2[3 * j + 1] - py;
        dzs[n] = pos2[3 * j + 2] - pz;
    }
    __syncthreads();

    // ---- pass 1: rows split in 4 quarters; col = tid % 128 ----
    {
        int c  = tid & 127;
        int rh = tid >> 7;                  // 0..3 -> rows rh*12 .. rh*12+11
        float wx = W1[64 * H1 + c], wy = W1[65 * H1 + c], wz = W1[66 * H1 + c];
        int ks = c >> 3;
        #pragma unroll
        for (int r = 0; r < 12; ++r) {
            int n = rh * 12 + r;
            float t = g_y2[(size_t)jb[n] * H1 + c];
            t = fmaf(dxs[n], wx, t);
            t = fmaf(dys[n], wy, t);
            t = fmaf(dzs[n], wz, t);
            float v = fmaxf(t, 0.0f);
            int mt = n >> 4;
            int rl = n & 15;
            int tt = ((rl & 7) << 2) | (c & 3);
            int w  = (rl >> 3) | (((c >> 2) & 1) << 1);
            afrag[((mt * KS + ks) * 32 + tt) * 4 + w] = tf32r(v);
        }
    }
    __syncthreads();

    // ---- pass 2: tf32 mma, 6 per k-step per warp ----
    int g = tid >> 5;          // warp 0..15: col group (g>>1)*32, nt pair g&1
    int t = tid & 31;

    float acc[MT][2][4];
    #pragma unroll
    for (int mt = 0; mt < MT; ++mt)
        #pragma unroll
        for (int nt = 0; nt < 2; ++nt)
            #pragma unroll
            for (int i = 0; i < 4; ++i) acc[mt][nt][i] = 0.0f;

    #pragma unroll 4
    for (int ks = 0; ks < KS; ++ks) {
        uint4 a[MT];
        #pragma unroll
        for (int mt = 0; mt < MT; ++mt)
            a[mt] = *(const uint4*)&afrag[((mt * KS + ks) * 32 + t) * 4];
        size_t bofs = ((size_t)(ks * 8 + (g >> 1)) * 32 + t) * 8 + (g & 1) * 4;
        uint4 bb = *(const uint4*)&g_bh[bofs];
        #pragma unroll
        for (int mt = 0; mt < MT; ++mt) {
            mma_tf32(acc[mt][0], a[mt].x, a[mt].y, a[mt].z, a[mt].w, bb.x, bb.y);
            mma_tf32(acc[mt][1], a[mt].x, a[mt].y, a[mt].z, a[mt].w, bb.z, bb.w);
        }
    }

    // ---- epilogue: max over rows (pads are dup self -> no masking) ----
    #pragma unroll
    for (int nt = 0; nt < 2; ++nt) {
        float vA = acc[0][nt][0], vB = acc[0][nt][1];
        vA = fmaxf(vA, acc[0][nt][2]);  vB = fmaxf(vB, acc[0][nt][3]);
        #pragma unroll
        for (int mt = 1; mt < MT; ++mt) {
            vA = fmaxf(vA, fmaxf(acc[mt][nt][0], acc[mt][nt][2]));
            vB = fmaxf(vB, fmaxf(acc[mt][nt][1], acc[mt][nt][3]));
        }
        #pragma unroll
        for (int o = 4; o < 32; o <<= 1) {
            vA = fmaxf(vA, __shfl_xor_sync(0xffffffffu, vA, o));
            vB = fmaxf(vB, __shfl_xor_sync(0xffffffffu, vB, o));
        }
        if (t < 4) {
            int colA = (g >> 1) * 32 + ((g & 1) * 2 + nt) * 8 + t * 2;
            out[(size_t)q * H2 + colA]     = fmaxf(vA + b2[colA], 0.0f);
            out[(size_t)q * H2 + colA + 1] = fmaxf(vB + b2[colA + 1], 0.0f);
        }
    }
}

// =========================== launcher ======================================
extern "C" void kernel_launch(void* const* d_in, const int* in_sizes, int n_in,
                              void* d_out, int out_size)
{
    // inputs: 0:x1 1:pos1 2:batch1(i64) 3:x2 4:pos2 5:batch2(i64)
    //         6:W1[67,128] 7:b1[128] 8:W2[128,256] 9:b2[256]
    const float* pos1 = (const float*)d_in[1];
    const float* x2   = (const float*)d_in[3];
    const float* pos2 = (const float*)d_in[4];
    const float* W1   = (const float*)d_in[6];
    const float* b1   = (const float*)d_in[7];
    const float* W2   = (const float*)d_in[8];
    const float* b2   = (const float*)d_in[9];
    float* out = (float*)d_out;

    precompute_y2_kernel<<<N2 / PR_ROWS, 128>>>(x2, W1, b1);
    bfrag_kernel<<<KS * 8 * 32 * 8 / 256, 256>>>(W2);
    ball_query_kernel<<<(N1 * 32 + 255) / 256, 256>>>(pos1, pos2);
    conv_kernel<<<N1, CT>>>(pos1, pos2, W1, b2, out);
}

// round 10
// speedup vs baseline: 2.0943x; 1.2813x over previous
#include <cuda_runtime.h>
#include <cuda_bf16.h>

// Problem constants
#define B     16
#define N1P   1024
#define N2P   4096
#define N1    (B * N1P)      // 16384 queries
#define N2    (B * N2P)      // 65536 sources
#define D_IN  64
#define H1    128
#define H2    256
#define KNB   32
#define R2    0.04f

#define MT    2              // neighbor m-tiles per query (32 rows)
#define KS    16             // k-steps (128 / 8)

typedef unsigned int uint;

// ---------------- scratch (static device globals; no allocations) ----------
__device__ float g_y2[(size_t)N2 * H1];     // x2 @ W1[:64] + b1  (33.5 MB)
__device__ int   g_nbr[(size_t)N1 * KNB];
__device__ int   g_cnt[N1];
__device__ uint  g_bh[KS * 8 * 32 * 8];     // W2 tf32 fragments (128 KB)
__device__ float g_self[(size_t)N1 * H2];   // self-row @ W2, raw (16 MB)

// ---------------- tf32 helpers ---------------------------------------------
__device__ __forceinline__ uint tf32r(float f) {
    uint u; asm("cvt.rna.tf32.f32 %0, %1;" : "=r"(u) : "f"(f)); return u;
}
__device__ __forceinline__ void mma_tf32(float* c, uint a0, uint a1, uint a2,
                                         uint a3, uint b0, uint b1) {
    asm("mma.sync.aligned.m16n8k8.row.col.f32.tf32.tf32.f32 "
        "{%0,%1,%2,%3},{%4,%5,%6,%7},{%8,%9},{%0,%1,%2,%3};"
        : "+f"(c[0]), "+f"(c[1]), "+f"(c[2]), "+f"(c[3])
        : "r"(a0), "r"(a1), "r"(a2), "r"(a3), "r"(b0), "r"(b1));
}

// ================ kernel 1: y2 = x2 @ W1[0:64] + b1 ========================
#define PR_ROWS 64
__global__ __launch_bounds__(128) void precompute_y2_kernel(
    const float* __restrict__ x2, const float* __restrict__ W1,
    const float* __restrict__ b1)
{
    __shared__ __align__(16) float xs[PR_ROWS * D_IN];
    int c = threadIdx.x;
    float w[D_IN];
    #pragma unroll
    for (int d = 0; d < D_IN; ++d) w[d] = W1[d * H1 + c];
    float bc = b1[c];

    size_t rbase = (size_t)blockIdx.x * PR_ROWS;
    const float4* src  = (const float4*)(x2 + rbase * D_IN);
    float4*       dst4 = (float4*)xs;
    for (int i = c; i < PR_ROWS * D_IN / 4; i += 128) dst4[i] = src[i];
    __syncthreads();

    for (int r = 0; r < PR_ROWS; ++r) {
        const float4* xr = (const float4*)(xs + r * D_IN);
        float a = bc;
        #pragma unroll
        for (int t = 0; t < D_IN / 4; ++t) {
            float4 xv = xr[t];
            a = fmaf(xv.x, w[4 * t],     a);
            a = fmaf(xv.y, w[4 * t + 1], a);
            a = fmaf(xv.z, w[4 * t + 2], a);
            a = fmaf(xv.w, w[4 * t + 3], a);
        }
        g_y2[(rbase + r) * H1 + c] = a;
    }
}

// ================ kernel 1b: W2 -> tf32 fragment layout ====================
// idx i -> [((ks*8+G)*32 + t)*8 + w]; w = NT*2+word;  (G: 32-col group 0..7)
// source element: W2[8*ks + (t%4) + 4*word][G*32 + NT*8 + t/4]
__global__ __launch_bounds__(256) void bfrag_kernel(const float* __restrict__ W2)
{
    int i = blockIdx.x * 256 + threadIdx.x;         // 32768 total
    int w    = i & 7;
    int t    = (i >> 3) & 31;
    int g    = (i >> 8) & 7;
    int ks   = i >> 11;
    int nt   = w >> 1;
    int word = w & 1;
    int k = 8 * ks + (t & 3) + 4 * word;
    int n = g * 32 + nt * 8 + (t >> 2);
    g_bh[i] = tf32r(W2[k * H2 + n]);
}

// ================ kernel 2: ball query (warp per query) ====================
__global__ void ball_query_kernel(const float* __restrict__ pos1,
                                  const float* __restrict__ pos2)
{
    int gw   = (blockIdx.x * blockDim.x + threadIdx.x) >> 5;
    int lane = threadIdx.x & 31;
    if (gw >= N1) return;
    int q = gw;
    float qx = pos1[3 * q], qy = pos1[3 * q + 1], qz = pos1[3 * q + 2];
    float qn = qx * qx + qy * qy + qz * qz;
    int base = (q >> 10) << 12;
    int cnt = 0;
    for (int chunk = 0; chunk < N2P / 32; ++chunk) {
        int s = base + chunk * 32 + lane;
        float sx = pos2[3 * s], sy = pos2[3 * s + 1], sz = pos2[3 * s + 2];
        float sn  = sx * sx + sy * sy + sz * sz;
        float dot = qx * sx + qy * sy + qz * sz;
        float sq  = qn + sn - 2.0f * dot;
        bool inb = (sq <= R2);
        unsigned m = __ballot_sync(0xffffffffu, inb);
        if (inb) {
            int slot = cnt + __popc(m & ((1u << lane) - 1u));
            if (slot < KNB) g_nbr[(size_t)q * KNB + slot] = s;
        }
        cnt += __popc(m);
        if (cnt >= KNB) break;
    }
    if (lane == 0) g_cnt[q] = (cnt < KNB) ? cnt : KNB;
}

// ================ kernel 2b: dense self-row GEMM ===========================
// g_self[q][:] = m1_self[q] @ W2  (raw, no bias/relu) where
// m1_self[q][k] = relu(y2[q][k] + (pos2[q]-pos1[q]) . W1[64:67,k]).
// CTA: 64 queries (4 m-tiles), 256 threads, 8 warps x 32 cols.
__global__ __launch_bounds__(256) void self_gemm_kernel(
    const float* __restrict__ pos1, const float* __restrict__ pos2,
    const float* __restrict__ W1)
{
    __shared__ __align__(16) uint afrag[4 * KS * 32 * 4];   // 32 KB
    __shared__ float dxs[64], dys[64], dzs[64];

    int tid   = threadIdx.x;
    int qbase = blockIdx.x * 64;

    if (tid < 64) {
        int q0 = qbase + tid;
        dxs[tid] = pos2[3 * q0]     - pos1[3 * q0];
        dys[tid] = pos2[3 * q0 + 1] - pos1[3 * q0 + 1];
        dzs[tid] = pos2[3 * q0 + 2] - pos1[3 * q0 + 2];
    }
    __syncthreads();

    {
        int c  = tid & 127;
        int rh = tid >> 7;              // 0,1 -> rows rh*32 .. rh*32+31
        float wx = W1[64 * H1 + c], wy = W1[65 * H1 + c], wz = W1[66 * H1 + c];
        int ks = c >> 3;
        #pragma unroll
        for (int r = 0; r < 32; ++r) {
            int n = rh * 32 + r;
            float t = g_y2[(size_t)(qbase + n) * H1 + c];
            t = fmaf(dxs[n], wx, t);
            t = fmaf(dys[n], wy, t);
            t = fmaf(dzs[n], wz, t);
            float v = fmaxf(t, 0.0f);
            int mt = n >> 4;
            int rl = n & 15;
            int tt = ((rl & 7) << 2) | (c & 3);
            int w  = (rl >> 3) | (((c >> 2) & 1) << 1);
            afrag[((mt * KS + ks) * 32 + tt) * 4 + w] = tf32r(v);
        }
    }
    __syncthreads();

    int g = tid >> 5;
    int t = tid & 31;

    float acc[4][4][4];
    #pragma unroll
    for (int mt = 0; mt < 4; ++mt)
        #pragma unroll
        for (int nt = 0; nt < 4; ++nt)
            #pragma unroll
            for (int i = 0; i < 4; ++i) acc[mt][nt][i] = 0.0f;

    for (int ks = 0; ks < KS; ++ks) {
        uint4 a[4];
        #pragma unroll
        for (int mt = 0; mt < 4; ++mt)
            a[mt] = *(const uint4*)&afrag[((mt * KS + ks) * 32 + t) * 4];
        size_t bofs = ((size_t)(ks * 8 + g) * 32 + t) * 8;
        uint4 b01 = *(const uint4*)&g_bh[bofs];
        uint4 b23 = *(const uint4*)&g_bh[bofs + 4];
        #pragma unroll
        for (int mt = 0; mt < 4; ++mt) {
            mma_tf32(acc[mt][0], a[mt].x, a[mt].y, a[mt].z, a[mt].w, b01.x, b01.y);
            mma_tf32(acc[mt][1], a[mt].x, a[mt].y, a[mt].z, a[mt].w, b01.z, b01.w);
            mma_tf32(acc[mt][2], a[mt].x, a[mt].y, a[mt].z, a[mt].w, b23.x, b23.y);
            mma_tf32(acc[mt][3], a[mt].x, a[mt].y, a[mt].z, a[mt].w, b23.z, b23.w);
        }
    }

    // store raw results: lane t -> rows t/4 and t/4+8, cols (t%4)*2, +1
    #pragma unroll
    for (int mt = 0; mt < 4; ++mt) {
        int r0 = qbase + mt * 16 + (t >> 2);
        #pragma unroll
        for (int nt = 0; nt < 4; ++nt) {
            int col = g * 32 + nt * 8 + (t & 3) * 2;
            g_self[(size_t)r0 * H2 + col]           = acc[mt][nt][0];
            g_self[(size_t)r0 * H2 + col + 1]       = acc[mt][nt][1];
            g_self[(size_t)(r0 + 8) * H2 + col]     = acc[mt][nt][2];
            g_self[(size_t)(r0 + 8) * H2 + col + 1] = acc[mt][nt][3];
        }
    }
}

// ================ kernel 3: per-query neighbor MLP via tf32 mma ============
// 256 threads / query, 8 warps x 32 cols (4 n-tiles). MT=2 (32 nbr rows,
// pads = dup self row — harmless, self covered by g_self in epilogue).
__global__ __launch_bounds__(256, 4) void conv_kernel(
    const float* __restrict__ pos1, const float* __restrict__ pos2,
    const float* __restrict__ W1,   const float* __restrict__ b2,
    float* __restrict__ out)
{
    __shared__ __align__(16) uint afrag[MT * KS * 32 * 4];  // 16 KB
    __shared__ int   jb[KNB];
    __shared__ float dxs[KNB], dys[KNB], dzs[KNB];

    int q   = blockIdx.x;
    int tid = threadIdx.x;
    int cnt = g_cnt[q];

    if (tid < KNB) {
        int n = tid;
        int j = (n < cnt) ? g_nbr[(size_t)q * KNB + n] : q;  // pad -> self
        jb[n] = j;
        float px = pos1[3 * q], py = pos1[3 * q + 1], pz = pos1[3 * q + 2];
        dxs[n] = pos2[3 * j]     - px;
        dys[n] = pos2[3 * j + 1] - py;
        dzs[n] = pos2[3 * j + 2] - pz;
    }
    __syncthreads();

    // ---- pass 1: 32 rows, split in 2 halves; col = tid % 128 ----
    {
        int c  = tid & 127;
        int rh = tid >> 7;                  // 0,1 -> rows rh*16 .. rh*16+15
        float wx = W1[64 * H1 + c], wy = W1[65 * H1 + c], wz = W1[66 * H1 + c];
        int ks = c >> 3;
        #pragma unroll
        for (int r = 0; r < 16; ++r) {
            int n = rh * 16 + r;
            float t = g_y2[(size_t)jb[n] * H1 + c];
            t = fmaf(dxs[n], wx, t);
            t = fmaf(dys[n], wy, t);
            t = fmaf(dzs[n], wz, t);
            float v = fmaxf(t, 0.0f);
            int mt = n >> 4;
            int rl = n & 15;
            int tt = ((rl & 7) << 2) | (c & 3);
            int w  = (rl >> 3) | (((c >> 2) & 1) << 1);
            afrag[((mt * KS + ks) * 32 + tt) * 4 + w] = tf32r(v);
        }
    }
    __syncthreads();

    // ---- pass 2: 8 mma per k-step per warp ----
    int g = tid >> 5;
    int t = tid & 31;

    float acc[MT][4][4];
    #pragma unroll
    for (int mt = 0; mt < MT; ++mt)
        #pragma unroll
        for (int nt = 0; nt < 4; ++nt)
            #pragma unroll
            for (int i = 0; i < 4; ++i) acc[mt][nt][i] = 0.0f;

    #pragma unroll 4
    for (int ks = 0; ks < KS; ++ks) {
        uint4 a[MT];
        #pragma unroll
        for (int mt = 0; mt < MT; ++mt)
            a[mt] = *(const uint4*)&afrag[((mt * KS + ks) * 32 + t) * 4];
        size_t bofs = ((size_t)(ks * 8 + g) * 32 + t) * 8;
        uint4 b01 = *(const uint4*)&g_bh[bofs];
        uint4 b23 = *(const uint4*)&g_bh[bofs + 4];
        #pragma unroll
        for (int mt = 0; mt < MT; ++mt) {
            mma_tf32(acc[mt][0], a[mt].x, a[mt].y, a[mt].z, a[mt].w, b01.x, b01.y);
            mma_tf32(acc[mt][1], a[mt].x, a[mt].y, a[mt].z, a[mt].w, b01.z, b01.w);
            mma_tf32(acc[mt][2], a[mt].x, a[mt].y, a[mt].z, a[mt].w, b23.x, b23.y);
            mma_tf32(acc[mt][3], a[mt].x, a[mt].y, a[mt].z, a[mt].w, b23.z, b23.w);
        }
    }

    // ---- epilogue: max over neighbor rows + self (g_self), bias, relu ----
    #pragma unroll
    for (int nt = 0; nt < 4; ++nt) {
        float vA = fmaxf(acc[0][nt][0], acc[0][nt][2]);
        float vB = fmaxf(acc[0][nt][1], acc[0][nt][3]);
        vA = fmaxf(vA, fmaxf(acc[1][nt][0], acc[1][nt][2]));
        vB = fmaxf(vB, fmaxf(acc[1][nt][1], acc[1][nt][3]));
        #pragma unroll
        for (int o = 4; o < 32; o <<= 1) {
            vA = fmaxf(vA, __shfl_xor_sync(0xffffffffu, vA, o));
            vB = fmaxf(vB, __shfl_xor_sync(0xffffffffu, vB, o));
        }
        if (t < 4) {
            int colA = g * 32 + nt * 8 + t * 2;
            vA = fmaxf(vA, g_self[(size_t)q * H2 + colA]);
            vB = fmaxf(vB, g_self[(size_t)q * H2 + colA + 1]);
            out[(size_t)q * H2 + colA]     = fmaxf(vA + b2[colA], 0.0f);
            out[(size_t)q * H2 + colA + 1] = fmaxf(vB + b2[colA + 1], 0.0f);
        }
    }
}

// =========================== launcher ======================================
extern "C" void kernel_launch(void* const* d_in, const int* in_sizes, int n_in,
                              void* d_out, int out_size)
{
    // inputs: 0:x1 1:pos1 2:batch1(i64) 3:x2 4:pos2 5:batch2(i64)
    //         6:W1[67,128] 7:b1[128] 8:W2[128,256] 9:b2[256]
    const float* pos1 = (const float*)d_in[1];
    const float* x2   = (const float*)d_in[3];
    const float* pos2 = (const float*)d_in[4];
    const float* W1   = (const float*)d_in[6];
    const float* b1   = (const float*)d_in[7];
    const float* W2   = (const float*)d_in[8];
    const float* b2   = (const float*)d_in[9];
    float* out = (float*)d_out;

    precompute_y2_kernel<<<N2 / PR_ROWS, 128>>>(x2, W1, b1);
    bfrag_kernel<<<KS * 8 * 32 * 8 / 256, 256>>>(W2);
    ball_query_kernel<<<(N1 * 32 + 255) / 256, 256>>>(pos1, pos2);
    self_gemm_kernel<<<N1 / 64, 256>>>(pos1, pos2, W1);
    conv_kernel<<<N1, 256>>>(pos1, pos2, W1, b2, out);
}